// round 4
// baseline (speedup 1.0000x reference)
#include <cuda_runtime.h>
#include <math.h>

// Problem constants
#define B_    2
#define L_    13294
#define S_    13294
#define D_    256
#define NH_   8
#define HD_   32
#define M_    (B_ * L_)          // 26588 rows for all GEMMs

// Scratch (static device arrays — no allocation allowed)
__device__ float g_val  [(size_t)M_ * 256];  // value @ W_val   [B,S,NH,HD]
__device__ float g_off  [(size_t)M_ * 256];  // query @ W_off   [B,L,256]
__device__ float g_logit[(size_t)M_ * 128];  // query @ W_attn  [B,L,128]
__device__ float g_acc  [(size_t)M_ * 256];  // sampled output  [B,L,NH,HD]

// ---------------------------------------------------------------------------
// SGEMM with bias: C[M,N] = A[M,K] @ W[K,N] + b[N]
// 64x64 tile, BK=16, 256 threads, 4x4 microtile per thread.
// (Already at ~94% of the fp32 FFMA-issue ceiling; left unchanged this round.)
// ---------------------------------------------------------------------------
__global__ __launch_bounds__(256)
void sgemm_bias(const float* __restrict__ A, const float* __restrict__ W,
                const float* __restrict__ bias, float* __restrict__ C,
                int M, int N, int K) {
    __shared__ float As[16][64];
    __shared__ float Ws[16][64];

    const int t  = threadIdx.x;
    const int tx = t & 15;
    const int ty = t >> 4;
    const int m0 = blockIdx.y * 64;
    const int n0 = blockIdx.x * 64;

    const int arow = t >> 2;
    const int akg  = (t & 3) * 4;
    const int wrow = ty;
    const int wcol = tx * 4;

    float acc[4][4];
#pragma unroll
    for (int i = 0; i < 4; i++)
#pragma unroll
        for (int j = 0; j < 4; j++) acc[i][j] = 0.f;

    for (int k0 = 0; k0 < K; k0 += 16) {
        float4 a4 = make_float4(0.f, 0.f, 0.f, 0.f);
        if (m0 + arow < M)
            a4 = *(const float4*)&A[(size_t)(m0 + arow) * K + k0 + akg];
        As[akg + 0][arow] = a4.x;
        As[akg + 1][arow] = a4.y;
        As[akg + 2][arow] = a4.z;
        As[akg + 3][arow] = a4.w;

        float4 w4 = *(const float4*)&W[(size_t)(k0 + wrow) * N + n0 + wcol];
        *(float4*)&Ws[wrow][wcol] = w4;

        __syncthreads();

#pragma unroll
        for (int kk = 0; kk < 16; kk++) {
            float ra[4], rb[4];
#pragma unroll
            for (int i = 0; i < 4; i++) ra[i] = As[kk][ty * 4 + i];
#pragma unroll
            for (int j = 0; j < 4; j++) rb[j] = Ws[kk][tx * 4 + j];
#pragma unroll
            for (int i = 0; i < 4; i++)
#pragma unroll
                for (int j = 0; j < 4; j++)
                    acc[i][j] = fmaf(ra[i], rb[j], acc[i][j]);
        }
        __syncthreads();
    }

    float4 b4 = *(const float4*)&bias[n0 + tx * 4];
#pragma unroll
    for (int i = 0; i < 4; i++) {
        int row = m0 + ty * 4 + i;
        if (row < M) {
            float4 o;
            o.x = acc[i][0] + b4.x;
            o.y = acc[i][1] + b4.y;
            o.z = acc[i][2] + b4.z;
            o.w = acc[i][3] + b4.w;
            *(float4*)&C[(size_t)row * N + n0 + tx * 4] = o;
        }
    }
}

// ---------------------------------------------------------------------------
// Deformable sampling, 4-heads-per-warp version.
// Warp layout: 4 groups x 8 lanes. group g = lane>>3 picks head h = hq*4+g.
// Each lane owns 4 channels (float4 path). All per-sample scalar math is
// shared across the 4 heads (1 warp-instruction serves 4 head-samples).
// Corner loads: 1x LDG.128 per head-sample + 3 immediate-offset LDG.128.
// ---------------------------------------------------------------------------
__global__ __launch_bounds__(256)
void deform_sample4(const float* __restrict__ ref,    // [B,L,4,2]
                    const float* __restrict__ offs,   // [B,L,256]
                    const float* __restrict__ logit,  // [B,L,128]
                    const float* __restrict__ val,    // [B,S,NH,HD]
                    float* __restrict__ acc_out) {    // [B,L,NH,HD]
    const int warp = blockIdx.x * 8 + (threadIdx.x >> 5);
    const int lane = threadIdx.x & 31;
    if (warp >= M_ * 2) return;

    const int bq = warp >> 1;            // b*L + q
    const int b  = bq / L_;
    const int g  = lane >> 3;            // head within quad
    const int gl = lane & 7;             // channel group within head
    const int h  = (warp & 1) * 4 + g;
    const int ch = gl * 4;

    // ---- softmax over this head's 16 logits (2 per lane, 8 lanes/group) ----
    const float* lg = logit + (size_t)bq * 128 + h * 16;
    const float2 x2 = *(const float2*)(lg + gl * 2);
    float m = fmaxf(x2.x, x2.y);
#pragma unroll
    for (int o = 1; o < 8; o <<= 1)
        m = fmaxf(m, __shfl_xor_sync(0xffffffffu, m, o));
    const float ex = expf(x2.x - m);
    const float ey = expf(x2.y - m);
    float ssum = ex + ey;
#pragma unroll
    for (int o = 1; o < 8; o <<= 1)
        ssum += __shfl_xor_sync(0xffffffffu, ssum, o);
    const float inv = 1.f / ssum;
    const float wnx = ex * inv;          // weight of sample 2*gl
    const float wny = ey * inv;          // weight of sample 2*gl+1

    // ---- preload this head's 32 offset floats (samples 2gl, 2gl+1) ----
    const float4 off4 =
        *(const float4*)(offs + (size_t)bq * 256 + h * 32 + gl * 4);

    // ---- reference points (uniform across warp) ----
    const float* rp = ref + (size_t)bq * 8;
    const float4 r01 = *(const float4*)rp;        // levels 0,1
    const float4 r23 = *(const float4*)(rp + 4);  // levels 2,3
    const float rx_[4] = {r01.x, r01.z, r23.x, r23.z};
    const float ry_[4] = {r01.y, r01.w, r23.y, r23.w};

    const int HH[4] = {100, 50, 25, 13};
    const int ST[4] = {0, 10000, 12500, 13125};

    const float* vhead = val + (size_t)b * S_ * 256 + h * 32 + ch;

    float4 acc = make_float4(0.f, 0.f, 0.f, 0.f);
    const float4 z4 = make_float4(0.f, 0.f, 0.f, 0.f);

#pragma unroll
    for (int l = 0; l < 4; l++) {
        const int   Wd = HH[l];
        const float Wf = (float)Wd;
        const float rx = rx_[l];
        const float ry = ry_[l];
        const float* vrow = vhead + ST[l] * 256;

#pragma unroll
        for (int p = 0; p < 4; p++) {
            const int s   = l * 4 + p;
            const int src = s >> 1;
            float ox, oy, ws;
            if ((s & 1) == 0) {
                ox = __shfl_sync(0xffffffffu, off4.x, src, 8);
                oy = __shfl_sync(0xffffffffu, off4.y, src, 8);
                ws = __shfl_sync(0xffffffffu, wnx,   src, 8);
            } else {
                ox = __shfl_sync(0xffffffffu, off4.z, src, 8);
                oy = __shfl_sync(0xffffffffu, off4.w, src, 8);
                ws = __shfl_sync(0xffffffffu, wny,   src, 8);
            }

            const float xs = fmaf(rx, Wf, ox) - 0.5f;
            const float ys = fmaf(ry, Wf, oy) - 0.5f;
            const float x0f = floorf(xs);
            const float y0f = floorf(ys);
            const float fx = xs - x0f;
            const float fy = ys - y0f;
            const int x0 = (int)x0f;
            const int y0 = (int)y0f;

            const bool okx0 = (unsigned)x0       < (unsigned)Wd;
            const bool okx1 = (unsigned)(x0 + 1) < (unsigned)Wd;
            const bool oky0 = (unsigned)y0       < (unsigned)Wd;  // square lvls
            const bool oky1 = (unsigned)(y0 + 1) < (unsigned)Wd;

            const float gx0 = 1.f - fx;
            const float gy0 = 1.f - fy;
            const float u00 = ws * gx0 * gy0;
            const float u10 = ws * fx  * gy0;
            const float u01 = ws * gx0 * fy;
            const float u11 = ws * fx  * fy;

            // single base address; neighbors reached by immediate offsets
            const float* p00 = vrow + (y0 * Wd + x0) * 256;

            const float4 v00 = (okx0 && oky0) ? *(const float4*)(p00)                : z4;
            const float4 v10 = (okx1 && oky0) ? *(const float4*)(p00 + 256)          : z4;
            const float4 v01 = (okx0 && oky1) ? *(const float4*)(p00 + Wd * 256)     : z4;
            const float4 v11 = (okx1 && oky1) ? *(const float4*)(p00 + Wd * 256 + 256) : z4;

            acc.x += u00 * v00.x + u10 * v10.x + u01 * v01.x + u11 * v11.x;
            acc.y += u00 * v00.y + u10 * v10.y + u01 * v01.y + u11 * v11.y;
            acc.z += u00 * v00.z + u10 * v10.z + u01 * v01.z + u11 * v11.z;
            acc.w += u00 * v00.w + u10 * v10.w + u01 * v01.w + u11 * v11.w;
        }
    }

    *(float4*)(acc_out + (size_t)bq * 256 + h * 32 + ch) = acc;
}

// ---------------------------------------------------------------------------
extern "C" void kernel_launch(void* const* d_in, const int* in_sizes, int n_in,
                              void* d_out, int out_size) {
    const float* query  = (const float*)d_in[0];
    const float* refpt  = (const float*)d_in[1];
    const float* value  = (const float*)d_in[2];
    const float* W_val  = (const float*)d_in[3];
    const float* b_val  = (const float*)d_in[4];
    const float* W_off  = (const float*)d_in[5];
    const float* b_off  = (const float*)d_in[6];
    const float* W_attn = (const float*)d_in[7];
    const float* b_attn = (const float*)d_in[8];
    const float* W_out  = (const float*)d_in[9];
    const float* b_out  = (const float*)d_in[10];
    float* out = (float*)d_out;

    float *val_s, *off_s, *lg_s, *acc_s;
    cudaGetSymbolAddress((void**)&val_s, g_val);
    cudaGetSymbolAddress((void**)&off_s, g_off);
    cudaGetSymbolAddress((void**)&lg_s,  g_logit);
    cudaGetSymbolAddress((void**)&acc_s, g_acc);

    const int M = M_;
    dim3 blk(256);
    dim3 gN256(256 / 64, (M + 63) / 64);
    dim3 gN128(128 / 64, (M + 63) / 64);

    // Projections
    sgemm_bias<<<gN256, blk>>>(value, W_val, b_val, val_s, M, 256, 256);
    sgemm_bias<<<gN256, blk>>>(query, W_off, b_off, off_s, M, 256, 256);
    sgemm_bias<<<gN128, blk>>>(query, W_attn, b_attn, lg_s, M, 128, 256);

    // Deformable sampling: one warp per (b,q, head-quad)
    const int warps = M_ * 2;
    deform_sample4<<<(warps + 7) / 8, 256>>>(refpt, off_s, lg_s, val_s, acc_s);

    // Output projection -> d_out
    sgemm_bias<<<gN256, blk>>>(acc_s, W_out, b_out, out, M, 256, 256);
}

// round 5
// speedup vs baseline: 3.0771x; 3.0771x over previous
#include <cuda_runtime.h>
#include <math.h>
#include <stdint.h>

// Problem constants
#define B_    2
#define L_    13294
#define S_    13294
#define D_    256
#define NH_   8
#define HD_   32
#define M_    (B_ * L_)          // 26588 rows for all GEMMs

// Scratch (static device arrays — no allocation allowed)
__device__ float g_val  [(size_t)M_ * 256];  // value @ W_val   [B,S,NH,HD]
__device__ float g_off  [(size_t)M_ * 256];  // query @ W_off   [B,L,256]
__device__ float g_logit[(size_t)M_ * 128];  // query @ W_attn  [B,L,128]
__device__ float g_acc  [(size_t)M_ * 256];  // sampled output  [B,L,NH,HD]

__device__ __forceinline__ uint32_t f2tf32(float f) {
    uint32_t u;
    asm("cvt.rna.tf32.f32 %0, %1;" : "=r"(u) : "f"(f));
    return u;
}

// ---------------------------------------------------------------------------
// tf32 tensor-core GEMM with bias: C[M,N] = A[M,K] @ W[K,N] + b[N]
// Block tile 128x128, BK=16, 256 threads = 8 warps, warp tile 64x32.
// mma.sync.aligned.m16n8k8.row.col.f32.tf32.tf32.f32
// Requires K % 16 == 0, N % 128 == 0 (true here: K=256, N=256/128). M guarded.
// ---------------------------------------------------------------------------
__global__ __launch_bounds__(256, 2)
void gemm_tf32(const float* __restrict__ A, const float* __restrict__ W,
               const float* __restrict__ bias, float* __restrict__ C,
               int M, int N, int K) {
    // A tile: [128 rows][16 k] padded to stride 20 (conflict-free frag loads)
    // B tile: [16 k][128 n]   padded to stride 132
    __shared__ __align__(16) uint32_t As[128][20];
    __shared__ __align__(16) uint32_t Bs[16][132];

    const int t    = threadIdx.x;
    const int warp = t >> 5;
    const int lane = t & 31;
    const int g    = lane >> 2;   // groupID 0..7
    const int tg   = lane & 3;    // thread-in-group 0..3
    const int wm   = (warp & 1) * 64;   // warp row offset
    const int wn   = (warp >> 1) * 32;  // warp col offset

    const int m0 = blockIdx.y * 128;
    const int n0 = blockIdx.x * 128;

    // Global load mapping
    const int ar  = t >> 2;          // A row 0..63 (and +64)
    const int ak  = (t & 3) * 4;     // A k group
    const int br  = t >> 5;          // B k row 0..7 (and +8)
    const int bc  = (t & 31) * 4;    // B col group

    float4 av0, av1, bv0, bv1;

    auto load_tiles = [&](int k0) {
        const float4 z = make_float4(0.f, 0.f, 0.f, 0.f);
        int r0 = m0 + ar;
        av0 = (r0 < M) ? *(const float4*)&A[(size_t)r0 * K + k0 + ak] : z;
        int r1 = r0 + 64;
        av1 = (r1 < M) ? *(const float4*)&A[(size_t)r1 * K + k0 + ak] : z;
        bv0 = *(const float4*)&W[(size_t)(k0 + br)     * N + n0 + bc];
        bv1 = *(const float4*)&W[(size_t)(k0 + br + 8) * N + n0 + bc];
    };
    auto store_tiles = [&]() {
        uint4 u;
        u.x = f2tf32(av0.x); u.y = f2tf32(av0.y);
        u.z = f2tf32(av0.z); u.w = f2tf32(av0.w);
        *(uint4*)&As[ar][ak] = u;
        u.x = f2tf32(av1.x); u.y = f2tf32(av1.y);
        u.z = f2tf32(av1.z); u.w = f2tf32(av1.w);
        *(uint4*)&As[ar + 64][ak] = u;
        u.x = f2tf32(bv0.x); u.y = f2tf32(bv0.y);
        u.z = f2tf32(bv0.z); u.w = f2tf32(bv0.w);
        *(uint4*)&Bs[br][bc] = u;
        u.x = f2tf32(bv1.x); u.y = f2tf32(bv1.y);
        u.z = f2tf32(bv1.z); u.w = f2tf32(bv1.w);
        *(uint4*)&Bs[br + 8][bc] = u;
    };

    float acc[4][4][4];
#pragma unroll
    for (int i = 0; i < 4; i++)
#pragma unroll
        for (int j = 0; j < 4; j++)
#pragma unroll
            for (int r = 0; r < 4; r++) acc[i][j][r] = 0.f;

    const int niter = K / 16;
    load_tiles(0);
    store_tiles();
    __syncthreads();

    for (int it = 0; it < niter; ++it) {
        const bool more = (it + 1) < niter;
        if (more) load_tiles((it + 1) * 16);

#pragma unroll
        for (int ks = 0; ks < 2; ks++) {
            const int kb = ks * 8;
            uint32_t af[4][4], bf[4][2];
#pragma unroll
            for (int mt = 0; mt < 4; mt++) {
                const int r = wm + mt * 16 + g;
                af[mt][0] = As[r    ][kb + tg];
                af[mt][1] = As[r + 8][kb + tg];
                af[mt][2] = As[r    ][kb + tg + 4];
                af[mt][3] = As[r + 8][kb + tg + 4];
            }
#pragma unroll
            for (int nt = 0; nt < 4; nt++) {
                const int c = wn + nt * 8 + g;
                bf[nt][0] = Bs[kb + tg    ][c];
                bf[nt][1] = Bs[kb + tg + 4][c];
            }
#pragma unroll
            for (int mt = 0; mt < 4; mt++)
#pragma unroll
                for (int nt = 0; nt < 4; nt++) {
                    asm volatile(
                        "mma.sync.aligned.m16n8k8.row.col.f32.tf32.tf32.f32 "
                        "{%0,%1,%2,%3}, {%4,%5,%6,%7}, {%8,%9}, {%0,%1,%2,%3};"
                        : "+f"(acc[mt][nt][0]), "+f"(acc[mt][nt][1]),
                          "+f"(acc[mt][nt][2]), "+f"(acc[mt][nt][3])
                        : "r"(af[mt][0]), "r"(af[mt][1]),
                          "r"(af[mt][2]), "r"(af[mt][3]),
                          "r"(bf[nt][0]), "r"(bf[nt][1]));
                }
        }

        __syncthreads();
        if (more) {
            store_tiles();
            __syncthreads();
        }
    }

    // Epilogue: bias add + store (float2 per fragment row)
#pragma unroll
    for (int nt = 0; nt < 4; nt++) {
        const int c = n0 + wn + nt * 8 + tg * 2;
        const float2 bb = *(const float2*)&bias[c];
#pragma unroll
        for (int mt = 0; mt < 4; mt++) {
            const int r0 = m0 + wm + mt * 16 + g;
            if (r0 < M) {
                float2 o = make_float2(acc[mt][nt][0] + bb.x,
                                       acc[mt][nt][1] + bb.y);
                *(float2*)&C[(size_t)r0 * N + c] = o;
            }
            const int r1 = r0 + 8;
            if (r1 < M) {
                float2 o = make_float2(acc[mt][nt][2] + bb.x,
                                       acc[mt][nt][3] + bb.y);
                *(float2*)&C[(size_t)r1 * N + c] = o;
            }
        }
    }
}

// ---------------------------------------------------------------------------
// Deformable sampling, 4-heads-per-warp (R4 version — measured 156.5us).
// ---------------------------------------------------------------------------
__global__ __launch_bounds__(256)
void deform_sample4(const float* __restrict__ ref,    // [B,L,4,2]
                    const float* __restrict__ offs,   // [B,L,256]
                    const float* __restrict__ logit,  // [B,L,128]
                    const float* __restrict__ val,    // [B,S,NH,HD]
                    float* __restrict__ acc_out) {    // [B,L,NH,HD]
    const int warp = blockIdx.x * 8 + (threadIdx.x >> 5);
    const int lane = threadIdx.x & 31;
    if (warp >= M_ * 2) return;

    const int bq = warp >> 1;
    const int b  = bq / L_;
    const int g  = lane >> 3;
    const int gl = lane & 7;
    const int h  = (warp & 1) * 4 + g;
    const int ch = gl * 4;

    const float* lg = logit + (size_t)bq * 128 + h * 16;
    const float2 x2 = *(const float2*)(lg + gl * 2);
    float m = fmaxf(x2.x, x2.y);
#pragma unroll
    for (int o = 1; o < 8; o <<= 1)
        m = fmaxf(m, __shfl_xor_sync(0xffffffffu, m, o));
    const float ex = expf(x2.x - m);
    const float ey = expf(x2.y - m);
    float ssum = ex + ey;
#pragma unroll
    for (int o = 1; o < 8; o <<= 1)
        ssum += __shfl_xor_sync(0xffffffffu, ssum, o);
    const float inv = 1.f / ssum;
    const float wnx = ex * inv;
    const float wny = ey * inv;

    const float4 off4 =
        *(const float4*)(offs + (size_t)bq * 256 + h * 32 + gl * 4);

    const float* rp = ref + (size_t)bq * 8;
    const float4 r01 = *(const float4*)rp;
    const float4 r23 = *(const float4*)(rp + 4);
    const float rx_[4] = {r01.x, r01.z, r23.x, r23.z};
    const float ry_[4] = {r01.y, r01.w, r23.y, r23.w};

    const int HH[4] = {100, 50, 25, 13};
    const int ST[4] = {0, 10000, 12500, 13125};

    const float* vhead = val + (size_t)b * S_ * 256 + h * 32 + ch;

    float4 acc = make_float4(0.f, 0.f, 0.f, 0.f);
    const float4 z4 = make_float4(0.f, 0.f, 0.f, 0.f);

#pragma unroll
    for (int l = 0; l < 4; l++) {
        const int   Wd = HH[l];
        const float Wf = (float)Wd;
        const float rx = rx_[l];
        const float ry = ry_[l];
        const float* vrow = vhead + ST[l] * 256;

#pragma unroll
        for (int p = 0; p < 4; p++) {
            const int s   = l * 4 + p;
            const int src = s >> 1;
            float ox, oy, ws;
            if ((s & 1) == 0) {
                ox = __shfl_sync(0xffffffffu, off4.x, src, 8);
                oy = __shfl_sync(0xffffffffu, off4.y, src, 8);
                ws = __shfl_sync(0xffffffffu, wnx,   src, 8);
            } else {
                ox = __shfl_sync(0xffffffffu, off4.z, src, 8);
                oy = __shfl_sync(0xffffffffu, off4.w, src, 8);
                ws = __shfl_sync(0xffffffffu, wny,   src, 8);
            }

            const float xs = fmaf(rx, Wf, ox) - 0.5f;
            const float ys = fmaf(ry, Wf, oy) - 0.5f;
            const float x0f = floorf(xs);
            const float y0f = floorf(ys);
            const float fx = xs - x0f;
            const float fy = ys - y0f;
            const int x0 = (int)x0f;
            const int y0 = (int)y0f;

            const bool okx0 = (unsigned)x0       < (unsigned)Wd;
            const bool okx1 = (unsigned)(x0 + 1) < (unsigned)Wd;
            const bool oky0 = (unsigned)y0       < (unsigned)Wd;
            const bool oky1 = (unsigned)(y0 + 1) < (unsigned)Wd;

            const float gx0 = 1.f - fx;
            const float gy0 = 1.f - fy;
            const float u00 = ws * gx0 * gy0;
            const float u10 = ws * fx  * gy0;
            const float u01 = ws * gx0 * fy;
            const float u11 = ws * fx  * fy;

            const float* p00 = vrow + (y0 * Wd + x0) * 256;

            const float4 v00 = (okx0 && oky0) ? *(const float4*)(p00)                  : z4;
            const float4 v10 = (okx1 && oky0) ? *(const float4*)(p00 + 256)            : z4;
            const float4 v01 = (okx0 && oky1) ? *(const float4*)(p00 + Wd * 256)       : z4;
            const float4 v11 = (okx1 && oky1) ? *(const float4*)(p00 + Wd * 256 + 256) : z4;

            acc.x += u00 * v00.x + u10 * v10.x + u01 * v01.x + u11 * v11.x;
            acc.y += u00 * v00.y + u10 * v10.y + u01 * v01.y + u11 * v11.y;
            acc.z += u00 * v00.z + u10 * v10.z + u01 * v01.z + u11 * v11.z;
            acc.w += u00 * v00.w + u10 * v10.w + u01 * v01.w + u11 * v11.w;
        }
    }

    *(float4*)(acc_out + (size_t)bq * 256 + h * 32 + ch) = acc;
}

// ---------------------------------------------------------------------------
extern "C" void kernel_launch(void* const* d_in, const int* in_sizes, int n_in,
                              void* d_out, int out_size) {
    const float* query  = (const float*)d_in[0];
    const float* refpt  = (const float*)d_in[1];
    const float* value  = (const float*)d_in[2];
    const float* W_val  = (const float*)d_in[3];
    const float* b_val  = (const float*)d_in[4];
    const float* W_off  = (const float*)d_in[5];
    const float* b_off  = (const float*)d_in[6];
    const float* W_attn = (const float*)d_in[7];
    const float* b_attn = (const float*)d_in[8];
    const float* W_out  = (const float*)d_in[9];
    const float* b_out  = (const float*)d_in[10];
    float* out = (float*)d_out;

    float *val_s, *off_s, *lg_s, *acc_s;
    cudaGetSymbolAddress((void**)&val_s, g_val);
    cudaGetSymbolAddress((void**)&off_s, g_off);
    cudaGetSymbolAddress((void**)&lg_s,  g_logit);
    cudaGetSymbolAddress((void**)&acc_s, g_acc);

    const int M = M_;
    dim3 blk(256);
    dim3 gN256(256 / 128, (M + 127) / 128);
    dim3 gN128(128 / 128, (M + 127) / 128);

    // Projections (tf32 tensor cores)
    gemm_tf32<<<gN256, blk>>>(value, W_val, b_val, val_s, M, 256, 256);
    gemm_tf32<<<gN256, blk>>>(query, W_off, b_off, off_s, M, 256, 256);
    gemm_tf32<<<gN128, blk>>>(query, W_attn, b_attn, lg_s, M, 128, 256);

    // Deformable sampling: one warp per (b,q, head-quad)
    const int warps = M_ * 2;
    deform_sample4<<<(warps + 7) / 8, 256>>>(refpt, off_s, lg_s, val_s, acc_s);

    // Output projection -> d_out (tf32 tensor cores)
    gemm_tf32<<<gN256, blk>>>(acc_s, W_out, b_out, out, M, 256, 256);
}